// round 1
// baseline (speedup 1.0000x reference)
#include <cuda_runtime.h>
#include <mma.h>

using namespace nvcuda;

#define NN 4096
#define BM 128
#define BN 128
#define BK 16
#define LDT 20   // padded smem row stride in floats (80B: 16B-aligned, conflict-reducing)

// ---------------- scratch (static device globals; no allocation) ----------------
__device__ float g_xs[(size_t)NN * NN];   // softmaxed x, tf32-rounded
__device__ float g_ys[(size_t)NN * NN];   // softmaxed y, tf32-rounded
__device__ float g_x2[NN];
__device__ float g_y2[NN];
__device__ float g_min_part[32 * NN];
__device__ float g_colmA[NN];             // per-column max of a = -10*C
__device__ float g_sum_part[32 * NN];
__device__ float g_w10[NN];               // log_nu - L_j  (== w_j / eps)
__device__ float g_cost_part[NN];

// ---------------- small helpers ----------------
__device__ __forceinline__ float to_tf32(float x) {
    unsigned u;
    asm("cvt.rna.tf32.f32 %0, %1;" : "=r"(u) : "f"(x));
    return __uint_as_float(u);
}

__device__ __forceinline__ void cp_async16(void* smem_dst, const void* gmem_src) {
    unsigned s = (unsigned)__cvta_generic_to_shared(smem_dst);
    asm volatile("cp.async.cg.shared.global [%0], [%1], 16;\n" :: "r"(s), "l"(gmem_src));
}
#define CP_COMMIT() asm volatile("cp.async.commit_group;\n" ::: "memory")
#define CP_WAIT1()  asm volatile("cp.async.wait_group 1;\n" ::: "memory")

// block-wide sum over 256 threads (deterministic fixed order)
__device__ __forceinline__ float blockSum256(float v) {
    __shared__ float sm[8];
    int lane = threadIdx.x & 31, w = threadIdx.x >> 5;
    #pragma unroll
    for (int o = 16; o > 0; o >>= 1) v += __shfl_xor_sync(0xffffffffu, v, o);
    if (lane == 0) sm[w] = v;
    __syncthreads();
    if (w == 0) {
        v = (lane < 8) ? sm[lane] : 0.0f;
        #pragma unroll
        for (int o = 4; o > 0; o >>= 1) v += __shfl_xor_sync(0xffffffffu, v, o);
        if (lane == 0) sm[0] = v;
    }
    __syncthreads();
    float r = sm[0];
    __syncthreads();
    return r;
}

__device__ __forceinline__ float blockMax256(float v) {
    __shared__ float sm[8];
    int lane = threadIdx.x & 31, w = threadIdx.x >> 5;
    #pragma unroll
    for (int o = 16; o > 0; o >>= 1) v = fmaxf(v, __shfl_xor_sync(0xffffffffu, v, o));
    if (lane == 0) sm[w] = v;
    __syncthreads();
    if (w == 0) {
        v = (lane < 8) ? sm[lane] : -3.4e38f;
        #pragma unroll
        for (int o = 4; o > 0; o >>= 1) v = fmaxf(v, __shfl_xor_sync(0xffffffffu, v, o));
        if (lane == 0) sm[0] = v;
    }
    __syncthreads();
    float r = sm[0];
    __syncthreads();
    return r;
}

// ---------------- 1) row softmax + sum of squares ----------------
// one block per row, 256 threads, 16 floats/thread held in registers
__global__ void softmax_kernel(const float* __restrict__ in, int which) {
    float* outp = which ? g_ys : g_xs;
    float* sq   = which ? g_y2 : g_x2;
    int row = blockIdx.x;
    const float4* rp = (const float4*)(in + (size_t)row * NN);
    float4* wp = (float4*)(outp + (size_t)row * NN);

    float4 v[4];
    #pragma unroll
    for (int i = 0; i < 4; i++) v[i] = rp[threadIdx.x + i * 256];

    float mx = -3.4e38f;
    #pragma unroll
    for (int i = 0; i < 4; i++) {
        mx = fmaxf(mx, fmaxf(fmaxf(v[i].x, v[i].y), fmaxf(v[i].z, v[i].w)));
    }
    mx = blockMax256(mx);

    float s = 0.0f;
    #pragma unroll
    for (int i = 0; i < 4; i++) {
        v[i].x = expf(v[i].x - mx); v[i].y = expf(v[i].y - mx);
        v[i].z = expf(v[i].z - mx); v[i].w = expf(v[i].w - mx);
        s += (v[i].x + v[i].y) + (v[i].z + v[i].w);
    }
    s = blockSum256(s);
    float inv = 1.0f / s;

    float q = 0.0f;
    #pragma unroll
    for (int i = 0; i < 4; i++) {
        float px = v[i].x * inv, py = v[i].y * inv, pz = v[i].z * inv, pw = v[i].w * inv;
        q += px * px + py * py + pz * pz + pw * pw;
        float4 o;
        o.x = to_tf32(px); o.y = to_tf32(py); o.z = to_tf32(pz); o.w = to_tf32(pw);
        wp[threadIdx.x + i * 256] = o;
    }
    q = blockSum256(q);
    if (threadIdx.x == 0) sq[row] = q;
}

// ---------------- 2) GEMM:  C[i,j] = x2[i] + y2[j] - 2 * sum_k Xs[i,k]*Ys[j,k] ----------------
__global__ __launch_bounds__(256) void gemm_kernel(float* __restrict__ C) {
    __shared__ __align__(16) float sA[2][BM][LDT];
    __shared__ __align__(16) float sB[2][BN][LDT];

    int tid = threadIdx.x;
    // grouped rasterization for L2 reuse
    int bid = blockIdx.x;
    const int TILES = NN / BM;   // 32
    const int GROUP = 8;
    int width = GROUP * TILES;
    int g = bid / width;
    int r = bid % width;
    int bm = g * GROUP + (r % GROUP);
    int bn = r / GROUP;
    int rowBase = bm * BM, colBase = bn * BN;

    int warpId = tid >> 5, lane = tid & 31;
    int wm = warpId & 3;   // 4 warps over M (32 rows each)
    int wn = warpId >> 2;  // 2 warps over N (64 cols each)

    wmma::fragment<wmma::accumulator, 16, 16, 8, float> acc[2][4];
    #pragma unroll
    for (int i = 0; i < 2; i++)
        #pragma unroll
        for (int j = 0; j < 4; j++) wmma::fill_fragment(acc[i][j], 0.0f);

    int ldrow = tid >> 2;            // 0..63
    int ldchunk = (tid & 3) * 4;     // 0,4,8,12 (floats)

    auto issue = [&](int stage, int k0) {
        #pragma unroll
        for (int w = 0; w < 2; w++) {
            int rr = ldrow + w * 64;
            cp_async16(&sA[stage][rr][ldchunk], g_xs + (size_t)(rowBase + rr) * NN + k0 + ldchunk);
            cp_async16(&sB[stage][rr][ldchunk], g_ys + (size_t)(colBase + rr) * NN + k0 + ldchunk);
        }
        CP_COMMIT();
    };

    issue(0, 0);
    const int KT = NN / BK;  // 256
    for (int kt = 0; kt < KT; kt++) {
        int cur = kt & 1;
        if (kt + 1 < KT) issue(cur ^ 1, (kt + 1) * BK);
        else CP_COMMIT();       // empty group keeps the wait count consistent
        CP_WAIT1();
        __syncthreads();

        #pragma unroll
        for (int kk = 0; kk < BK; kk += 8) {
            wmma::fragment<wmma::matrix_a, 16, 16, 8, wmma::precision::tf32, wmma::row_major> af[2];
            wmma::fragment<wmma::matrix_b, 16, 16, 8, wmma::precision::tf32, wmma::col_major> bf[4];
            #pragma unroll
            for (int i = 0; i < 2; i++)
                wmma::load_matrix_sync(af[i], &sA[cur][wm * 32 + i * 16][kk], LDT);
            #pragma unroll
            for (int j = 0; j < 4; j++)
                wmma::load_matrix_sync(bf[j], &sB[cur][wn * 64 + j * 16][kk], LDT);
            #pragma unroll
            for (int i = 0; i < 2; i++)
                #pragma unroll
                for (int j = 0; j < 4; j++)
                    wmma::mma_sync(acc[i][j], af[i], bf[j], acc[i][j]);
        }
        __syncthreads();
    }

    // epilogue: stage each 16x16 acc tile through smem (reuse sA), apply x2+y2-2g
    __syncthreads();
    float* stag = &sA[0][0][0] + warpId * 256;
    int rl = lane >> 1;
    int cl = (lane & 1) * 8;
    #pragma unroll
    for (int mi = 0; mi < 2; mi++) {
        #pragma unroll
        for (int nj = 0; nj < 4; nj++) {
            wmma::store_matrix_sync(stag, acc[mi][nj], 16, wmma::mem_row_major);
            __syncwarp();
            int gr = rowBase + wm * 32 + mi * 16 + rl;
            int gc = colBase + wn * 64 + nj * 16 + cl;
            float xv = g_x2[gr];
            float* cp = C + (size_t)gr * NN + gc;
            #pragma unroll
            for (int e = 0; e < 8; e++) {
                float gv = stag[rl * 16 + cl + e];
                cp[e] = xv + g_y2[gc + e] - 2.0f * gv;   // scalar: C base is 4B-odd in d_out
            }
            __syncwarp();
        }
    }
}

// ---------------- 3) column logsumexp of a = -C/eps = -10*C (two passes) ----------------
__global__ void colmin_kernel(const float* __restrict__ C) {
    int col = blockIdx.x * 256 + threadIdx.x;
    int r0 = blockIdx.y * 128;
    float m = 3.4e38f;
    #pragma unroll 4
    for (int r = 0; r < 128; r++) m = fminf(m, C[(size_t)(r0 + r) * NN + col]);
    g_min_part[blockIdx.y * NN + col] = m;
}

__global__ void combine_min_kernel() {
    int col = blockIdx.x * 256 + threadIdx.x;
    float m = 3.4e38f;
    #pragma unroll
    for (int i = 0; i < 32; i++) m = fminf(m, g_min_part[i * NN + col]);
    g_colmA[col] = -10.0f * m;   // max_i of (-10*C[i,col])
}

__global__ void colsum_kernel(const float* __restrict__ C) {
    int col = blockIdx.x * 256 + threadIdx.x;
    int r0 = blockIdx.y * 128;
    float mA = g_colmA[col];
    float s = 0.0f;
    #pragma unroll 4
    for (int r = 0; r < 128; r++) {
        float c = C[(size_t)(r0 + r) * NN + col];
        s += expf(fmaf(-10.0f, c, -mA));
    }
    g_sum_part[blockIdx.y * NN + col] = s;
}

__global__ void combine_sum_kernel() {
    int col = blockIdx.x * 256 + threadIdx.x;
    float S = 0.0f;
    #pragma unroll
    for (int i = 0; i < 32; i++) S += g_sum_part[i * NN + col];
    float L = g_colmA[col] + logf(S);
    float log_nu = logf(1.0f / 4096.0f + 1e-8f);
    g_w10[col] = log_nu - L;     // == w_j / eps
}

// ---------------- 4) pi = exp(-10*C + w10[j]); cost = sum(pi*C) ----------------
__global__ void pi_cost_kernel(const float* __restrict__ C, float* __restrict__ pi) {
    __shared__ float w[NN];
    int row = blockIdx.x;
    for (int i = threadIdx.x; i < NN; i += 256) w[i] = g_w10[i];
    __syncthreads();

    const float* cr = C + (size_t)row * NN;
    float* pr = pi + (size_t)row * NN;
    float lc = 0.0f;
    #pragma unroll
    for (int i = 0; i < 16; i++) {
        int j = threadIdx.x + i * 256;
        float c = cr[j];
        float p = expf(fmaf(-10.0f, c, w[j]));
        pr[j] = p;
        lc = fmaf(p, c, lc);
    }
    lc = blockSum256(lc);
    if (threadIdx.x == 0) g_cost_part[row] = lc;
}

__global__ void cost_final_kernel(float* __restrict__ out) {
    float s = 0.0f;
    for (int i = threadIdx.x; i < NN; i += 256) s += g_cost_part[i];
    s = blockSum256(s);
    if (threadIdx.x == 0) out[0] = s;
}

// ---------------- launch ----------------
extern "C" void kernel_launch(void* const* d_in, const int* in_sizes, int n_in,
                              void* d_out, int out_size) {
    const float* x = (const float*)d_in[0];
    const float* y = (const float*)d_in[1];
    float* out = (float*)d_out;
    float* pi = out + 1;                       // [N*N]
    float* C  = out + 1 + (size_t)NN * NN;     // [N*N]

    softmax_kernel<<<NN, 256>>>(x, 0);
    softmax_kernel<<<NN, 256>>>(y, 1);

    gemm_kernel<<<(NN / BM) * (NN / BN), 256>>>(C);

    colmin_kernel<<<dim3(NN / 256, 32), 256>>>(C);
    combine_min_kernel<<<NN / 256, 256>>>();
    colsum_kernel<<<dim3(NN / 256, 32), 256>>>(C);
    combine_sum_kernel<<<NN / 256, 256>>>();

    pi_cost_kernel<<<NN, 256>>>(C, pi);
    cost_final_kernel<<<1, 256>>>(out);
}

// round 3
// speedup vs baseline: 4.8689x; 4.8689x over previous
#include <cuda_runtime.h>
#include <cuda_fp16.h>
#include <cstdint>

#define NN 4096
#define SCALE 1024.0f
#define INV_S2 (1.0f / (1024.0f * 1024.0f))

// ---------------- scratch (static device globals; no allocation) ----------------
__device__ __half g_xs16[(size_t)NN * NN];   // softmaxed x * SCALE, fp16
__device__ __half g_ys16[(size_t)NN * NN];   // softmaxed y * SCALE, fp16
__device__ float g_x2[NN];
__device__ float g_y2[NN];
__device__ float g_sum_part[32 * NN];
__device__ float g_w10[NN];                  // log_nu - L_j  (== w_j / eps)
__device__ float g_cost_part[NN];

// ---------------- PTX helpers ----------------
__device__ __forceinline__ uint32_t smem_u32(const void* p) {
    uint32_t a;
    asm("{ .reg .u64 t; cvta.to.shared.u64 t, %1; cvt.u32.u64 %0, t; }" : "=r"(a) : "l"(p));
    return a;
}

__device__ __forceinline__ void cp_async16(uint32_t smem_dst, const void* gmem_src) {
    asm volatile("cp.async.cg.shared.global [%0], [%1], 16;\n" :: "r"(smem_dst), "l"(gmem_src));
}
#define CP_COMMIT() asm volatile("cp.async.commit_group;\n" ::: "memory")
#define CP_WAIT1()  asm volatile("cp.async.wait_group 1;\n" ::: "memory")
#define CP_WAIT0()  asm volatile("cp.async.wait_group 0;\n" ::: "memory")

#define LDSM_X4(r0, r1, r2, r3, addr) \
    asm volatile("ldmatrix.sync.aligned.m8n8.x4.shared.b16 {%0,%1,%2,%3}, [%4];" \
        : "=r"(r0), "=r"(r1), "=r"(r2), "=r"(r3) : "r"(addr))

#define MMA16816(d, a, b) \
    asm volatile("mma.sync.aligned.m16n8k16.row.col.f32.f16.f16.f32 " \
        "{%0,%1,%2,%3}, {%4,%5,%6,%7}, {%8,%9}, {%0,%1,%2,%3};" \
        : "+f"((d)[0]), "+f"((d)[1]), "+f"((d)[2]), "+f"((d)[3]) \
        : "r"((a)[0]), "r"((a)[1]), "r"((a)[2]), "r"((a)[3]), "r"((b)[0]), "r"((b)[1]))

// ---------------- block reductions ----------------
__device__ __forceinline__ float blockSum256(float v) {
    __shared__ float sm[8];
    int lane = threadIdx.x & 31, w = threadIdx.x >> 5;
    #pragma unroll
    for (int o = 16; o > 0; o >>= 1) v += __shfl_xor_sync(0xffffffffu, v, o);
    if (lane == 0) sm[w] = v;
    __syncthreads();
    if (w == 0) {
        v = (lane < 8) ? sm[lane] : 0.0f;
        #pragma unroll
        for (int o = 4; o > 0; o >>= 1) v += __shfl_xor_sync(0xffffffffu, v, o);
        if (lane == 0) sm[0] = v;
    }
    __syncthreads();
    float r = sm[0];
    __syncthreads();
    return r;
}

__device__ __forceinline__ float blockMax256(float v) {
    __shared__ float sm[8];
    int lane = threadIdx.x & 31, w = threadIdx.x >> 5;
    #pragma unroll
    for (int o = 16; o > 0; o >>= 1) v = fmaxf(v, __shfl_xor_sync(0xffffffffu, v, o));
    if (lane == 0) sm[w] = v;
    __syncthreads();
    if (w == 0) {
        v = (lane < 8) ? sm[lane] : -3.4e38f;
        #pragma unroll
        for (int o = 4; o > 0; o >>= 1) v = fmaxf(v, __shfl_xor_sync(0xffffffffu, v, o));
        if (lane == 0) sm[0] = v;
    }
    __syncthreads();
    float r = sm[0];
    __syncthreads();
    return r;
}

// ---------------- 1) row softmax -> fp16*SCALE + sum of squares ----------------
__global__ void softmax_kernel(const float* __restrict__ in, int which) {
    __half* outp = which ? g_ys16 : g_xs16;
    float* sq    = which ? g_y2 : g_x2;
    int row = blockIdx.x;
    const float4* rp = (const float4*)(in + (size_t)row * NN);
    uint2* wp = (uint2*)(outp + (size_t)row * NN);

    float4 v[4];
    #pragma unroll
    for (int i = 0; i < 4; i++) v[i] = rp[threadIdx.x + i * 256];

    float mx = -3.4e38f;
    #pragma unroll
    for (int i = 0; i < 4; i++)
        mx = fmaxf(mx, fmaxf(fmaxf(v[i].x, v[i].y), fmaxf(v[i].z, v[i].w)));
    mx = blockMax256(mx);

    float s = 0.0f;
    #pragma unroll
    for (int i = 0; i < 4; i++) {
        v[i].x = expf(v[i].x - mx); v[i].y = expf(v[i].y - mx);
        v[i].z = expf(v[i].z - mx); v[i].w = expf(v[i].w - mx);
        s += (v[i].x + v[i].y) + (v[i].z + v[i].w);
    }
    s = blockSum256(s);
    float inv = 1.0f / s;

    float q = 0.0f;
    #pragma unroll
    for (int i = 0; i < 4; i++) {
        float px = v[i].x * inv, py = v[i].y * inv, pz = v[i].z * inv, pw = v[i].w * inv;
        q += px * px + py * py + pz * pz + pw * pw;
        __half2 h0 = __floats2half2_rn(px * SCALE, py * SCALE);
        __half2 h1 = __floats2half2_rn(pz * SCALE, pw * SCALE);
        uint2 o;
        o.x = *(uint32_t*)&h0;
        o.y = *(uint32_t*)&h1;
        wp[threadIdx.x + i * 256] = o;
    }
    q = blockSum256(q);
    if (threadIdx.x == 0) sq[row] = q;
}

// ---------------- 2) fp16 mma.sync GEMM + epilogue C = x2+y2-2G ----------------
// CTA tile 128x128, K-chunk 64, 3-stage cp.async pipeline, 256 threads.
// Warps: 4(M) x 2(N), each warp owns 32x64 (2 m16 x 8 n8 mma tiles).
#define BKC 64
#define KT (NN / BKC)          // 64
#define STAGE_BYTES 32768u     // 16KB A + 16KB B
#define SMEM_TOTAL  (3 * STAGE_BYTES)   // 96KB

__global__ __launch_bounds__(256, 2) void gemm_kernel(float* __restrict__ C) {
    extern __shared__ __align__(128) char dyn[];
    uint32_t sbase = smem_u32(dyn);

    int tid = threadIdx.x, warp = tid >> 5, lane = tid & 31;

    // grouped rasterization for L2 reuse
    int bid = blockIdx.x;
    const int TILES = NN / 128;  // 32
    const int GROUP = 8;
    int width = GROUP * TILES;
    int g = bid / width;
    int r = bid % width;
    int bm = g * GROUP + (r % GROUP);
    int bn = r / GROUP;
    int rowBase = bm * 128, colBase = bn * 128;

    int wm = warp >> 1;        // 0..3  (M)
    int wn = warp & 1;         // 0..1  (N)

    float acc[2][8][4];
    #pragma unroll
    for (int mt = 0; mt < 2; mt++)
        #pragma unroll
        for (int nt = 0; nt < 8; nt++)
            #pragma unroll
            for (int e = 0; e < 4; e++) acc[mt][nt][e] = 0.0f;

    // cp.async mapping: thread t handles 4 chunks per tile (A and B same pattern)
    // linear = t + i*256 ; row = linear>>3 ; chunk = linear&7 ; swizzle chunk^=(row&7)
    auto issue = [&](int s, int kt) {
        uint32_t smA = sbase + (uint32_t)s * STAGE_BYTES;
        uint32_t smB = smA + 16384u;
        int k0 = kt * BKC;
        #pragma unroll
        for (int i = 0; i < 4; i++) {
            int lin = tid + i * 256;
            int row = lin >> 3, ch = lin & 7;
            uint32_t phys = (uint32_t)row * 128u + (uint32_t)((ch ^ (row & 7)) << 4);
            cp_async16(smA + phys, (const char*)(g_xs16 + (size_t)(rowBase + row) * NN + k0) + ch * 16);
            cp_async16(smB + phys, (const char*)(g_ys16 + (size_t)(colBase + row) * NN + k0) + ch * 16);
        }
        CP_COMMIT();
    };

    issue(0, 0);
    issue(1, 1);

    // precomputed ldmatrix lane bases
    int aRowSel = (lane & 7) + ((lane >> 3) & 1) * 8;   // row within m16 tile
    int aChSel  = (lane >> 4);                          // k8 chunk within k16
    int bColSel = ((lane >> 4) & 1) * 8 + (lane & 7);   // col within n16 pair
    int bChSel  = (lane >> 3) & 1;

    for (int kt = 0; kt < KT; kt++) {
        if (kt == KT - 1) { CP_WAIT0(); } else { CP_WAIT1(); }
        __syncthreads();
        if (kt + 2 < KT) issue((kt + 2) % 3, kt + 2);

        uint32_t aBase = sbase + (uint32_t)(kt % 3) * STAGE_BYTES;
        uint32_t bBase = aBase + 16384u;

        #pragma unroll
        for (int kk = 0; kk < 4; kk++) {
            uint32_t a[2][4];
            #pragma unroll
            for (int mt = 0; mt < 2; mt++) {
                int rowL = wm * 32 + mt * 16 + aRowSel;
                int ch = 2 * kk + aChSel;
                uint32_t addr = aBase + (uint32_t)rowL * 128u + (uint32_t)((ch ^ (rowL & 7)) << 4);
                LDSM_X4(a[mt][0], a[mt][1], a[mt][2], a[mt][3], addr);
            }
            uint32_t b[8][2];
            #pragma unroll
            for (int np = 0; np < 4; np++) {
                int colL = wn * 64 + np * 16 + bColSel;
                int ch = 2 * kk + bChSel;
                uint32_t addr = bBase + (uint32_t)colL * 128u + (uint32_t)((ch ^ (colL & 7)) << 4);
                uint32_t r0, r1, r2, r3;
                LDSM_X4(r0, r1, r2, r3, addr);
                b[2 * np][0] = r0; b[2 * np][1] = r1;
                b[2 * np + 1][0] = r2; b[2 * np + 1][1] = r3;
            }
            #pragma unroll
            for (int mt = 0; mt < 2; mt++)
                #pragma unroll
                for (int nt = 0; nt < 8; nt++)
                    MMA16816(acc[mt][nt], a[mt], b[nt]);
        }
        __syncthreads();
    }

    // ---------------- epilogue ----------------
    // stage 32x64 per warp in smem (stride 66), then coalesced row stores
    float* stg = (float*)dyn + warp * (32 * 66);
    int rsel = lane >> 2, csel = (lane & 3) * 2;
    #pragma unroll
    for (int mt = 0; mt < 2; mt++) {
        #pragma unroll
        for (int nt = 0; nt < 8; nt++) {
            stg[(mt * 16 + rsel) * 66 + nt * 8 + csel]     = acc[mt][nt][0];
            stg[(mt * 16 + rsel) * 66 + nt * 8 + csel + 1] = acc[mt][nt][1];
            stg[(mt * 16 + rsel + 8) * 66 + nt * 8 + csel]     = acc[mt][nt][2];
            stg[(mt * 16 + rsel + 8) * 66 + nt * 8 + csel + 1] = acc[mt][nt][3];
        }
    }
    __syncwarp();

    int growBase = rowBase + wm * 32;
    int gcol = colBase + wn * 64 + 2 * lane;
    float y0 = g_y2[gcol], y1 = g_y2[gcol + 1];
    #pragma unroll 4
    for (int rr = 0; rr < 32; rr++) {
        int grow = growBase + rr;
        float xv = g_x2[grow];
        float v0 = xv + y0 - 2.0f * INV_S2 * stg[rr * 66 + 2 * lane];
        float v1 = xv + y1 - 2.0f * INV_S2 * stg[rr * 66 + 2 * lane + 1];
        float* cp = C + (size_t)grow * NN + gcol;
        cp[0] = v0;
        cp[1] = v1;
    }
}

// ---------------- 3) column sums of exp(-10*C)  (no max shift needed: C small, >=0) ----------------
__global__ void colsum_kernel(const float* __restrict__ C) {
    int col = blockIdx.x * 256 + threadIdx.x;
    int r0 = blockIdx.y * 128;
    float s = 0.0f;
    #pragma unroll 16
    for (int r = 0; r < 128; r++) {
        float c = C[(size_t)(r0 + r) * NN + col];
        s += expf(-10.0f * c);
    }
    g_sum_part[blockIdx.y * NN + col] = s;
}

__global__ void combine_sum_kernel() {
    int col = blockIdx.x * 256 + threadIdx.x;
    float S = 0.0f;
    #pragma unroll
    for (int i = 0; i < 32; i++) S += g_sum_part[i * NN + col];
    float log_nu = logf(1.0f / 4096.0f + 1e-8f);
    g_w10[col] = log_nu - logf(S);
}

// ---------------- 4) pi = exp(-10*C + w10[j]); cost = sum(pi*C) ----------------
__global__ void pi_cost_kernel(const float* __restrict__ C, float* __restrict__ pi) {
    __shared__ float w[NN];
    int row = blockIdx.x;
    for (int i = threadIdx.x; i < NN; i += 256) w[i] = g_w10[i];
    __syncthreads();

    const float* cr = C + (size_t)row * NN;
    float* pr = pi + (size_t)row * NN;
    float lc = 0.0f;
    #pragma unroll
    for (int i = 0; i < 16; i++) {
        int j = threadIdx.x + i * 256;
        float c = cr[j];
        float p = expf(fmaf(-10.0f, c, w[j]));
        pr[j] = p;
        lc = fmaf(p, c, lc);
    }
    lc = blockSum256(lc);
    if (threadIdx.x == 0) g_cost_part[row] = lc;
}

__global__ void cost_final_kernel(float* __restrict__ out) {
    float s = 0.0f;
    for (int i = threadIdx.x; i < NN; i += 256) s += g_cost_part[i];
    s = blockSum256(s);
    if (threadIdx.x == 0) out[0] = s;
}

// ---------------- launch ----------------
extern "C" void kernel_launch(void* const* d_in, const int* in_sizes, int n_in,
                              void* d_out, int out_size) {
    const float* x = (const float*)d_in[0];
    const float* y = (const float*)d_in[1];
    float* out = (float*)d_out;
    float* pi = out + 1;                        // [N*N]
    float* C  = out + 1 + (size_t)NN * NN;      // [N*N]

    cudaFuncSetAttribute(gemm_kernel, cudaFuncAttributeMaxDynamicSharedMemorySize, SMEM_TOTAL);

    softmax_kernel<<<NN, 256>>>(x, 0);
    softmax_kernel<<<NN, 256>>>(y, 1);

    gemm_kernel<<<(NN / 128) * (NN / 128), 256, SMEM_TOTAL>>>(C);

    colsum_kernel<<<dim3(NN / 256, 32), 256>>>(C);
    combine_sum_kernel<<<NN / 256, 256>>>();

    pi_cost_kernel<<<NN, 256>>>(C, pi);
    cost_final_kernel<<<1, 256>>>(out);
}

// round 6
// speedup vs baseline: 4.9315x; 1.0128x over previous
#include <cuda_runtime.h>
#include <cuda_fp16.h>
#include <cstdint>

#define NN 4096
#define SCALE 1024.0f
#define INV_S2 (1.0f / (1024.0f * 1024.0f))

// ---------------- scratch (static device globals; no allocation) ----------------
__device__ __half g_xs16[(size_t)NN * NN];   // softmaxed x * SCALE, fp16
__device__ __half g_ys16[(size_t)NN * NN];   // softmaxed y * SCALE, fp16
__device__ float g_x2[NN];
__device__ float g_y2[NN];
__device__ float g_sum_part[32 * NN];
__device__ float g_w10[NN];                  // log_nu - L_j  (== w_j / eps)
__device__ float g_cost_part[NN];

// ---------------- PTX helpers ----------------
__device__ __forceinline__ uint32_t smem_u32(const void* p) {
    uint32_t a;
    asm("{ .reg .u64 t; cvta.to.shared.u64 t, %1; cvt.u32.u64 %0, t; }" : "=r"(a) : "l"(p));
    return a;
}

__device__ __forceinline__ void cp_async16(uint32_t smem_dst, const void* gmem_src) {
    asm volatile("cp.async.cg.shared.global [%0], [%1], 16;\n" :: "r"(smem_dst), "l"(gmem_src));
}
#define CP_COMMIT() asm volatile("cp.async.commit_group;\n" ::: "memory")
#define CP_WAIT2()  asm volatile("cp.async.wait_group 2;\n" ::: "memory")
#define CP_WAIT1()  asm volatile("cp.async.wait_group 1;\n" ::: "memory")
#define CP_WAIT0()  asm volatile("cp.async.wait_group 0;\n" ::: "memory")

#define LDSM_X4(r0, r1, r2, r3, addr) \
    asm volatile("ldmatrix.sync.aligned.m8n8.x4.shared.b16 {%0,%1,%2,%3}, [%4];" \
        : "=r"(r0), "=r"(r1), "=r"(r2), "=r"(r3) : "r"(addr))

#define MMA16816(d, a, b) \
    asm volatile("mma.sync.aligned.m16n8k16.row.col.f32.f16.f16.f32 " \
        "{%0,%1,%2,%3}, {%4,%5,%6,%7}, {%8,%9}, {%0,%1,%2,%3};" \
        : "+f"((d)[0]), "+f"((d)[1]), "+f"((d)[2]), "+f"((d)[3]) \
        : "r"((a)[0]), "r"((a)[1]), "r"((a)[2]), "r"((a)[3]), "r"((b)[0]), "r"((b)[1]))

// ---------------- block reductions ----------------
__device__ __forceinline__ float blockSum256(float v) {
    __shared__ float sm[8];
    int lane = threadIdx.x & 31, w = threadIdx.x >> 5;
    #pragma unroll
    for (int o = 16; o > 0; o >>= 1) v += __shfl_xor_sync(0xffffffffu, v, o);
    if (lane == 0) sm[w] = v;
    __syncthreads();
    if (w == 0) {
        v = (lane < 8) ? sm[lane] : 0.0f;
        #pragma unroll
        for (int o = 4; o > 0; o >>= 1) v += __shfl_xor_sync(0xffffffffu, v, o);
        if (lane == 0) sm[0] = v;
    }
    __syncthreads();
    float r = sm[0];
    __syncthreads();
    return r;
}

__device__ __forceinline__ float blockMax256(float v) {
    __shared__ float sm[8];
    int lane = threadIdx.x & 31, w = threadIdx.x >> 5;
    #pragma unroll
    for (int o = 16; o > 0; o >>= 1) v = fmaxf(v, __shfl_xor_sync(0xffffffffu, v, o));
    if (lane == 0) sm[w] = v;
    __syncthreads();
    if (w == 0) {
        v = (lane < 8) ? sm[lane] : -3.4e38f;
        #pragma unroll
        for (int o = 4; o > 0; o >>= 1) v = fmaxf(v, __shfl_xor_sync(0xffffffffu, v, o));
        if (lane == 0) sm[0] = v;
    }
    __syncthreads();
    float r = sm[0];
    __syncthreads();
    return r;
}

// ---------------- 1) row softmax -> fp16*SCALE + sum of squares (x and y in one grid) ----------------
__global__ void softmax_kernel(const float* __restrict__ xin, const float* __restrict__ yin) {
    int which = (blockIdx.x >= NN);
    int row = blockIdx.x - which * NN;
    const float* in = which ? yin : xin;
    __half* outp = which ? g_ys16 : g_xs16;
    float* sq    = which ? g_y2 : g_x2;
    const float4* rp = (const float4*)(in + (size_t)row * NN);
    uint2* wp = (uint2*)(outp + (size_t)row * NN);

    float4 v[4];
    #pragma unroll
    for (int i = 0; i < 4; i++) v[i] = rp[threadIdx.x + i * 256];

    float mx = -3.4e38f;
    #pragma unroll
    for (int i = 0; i < 4; i++)
        mx = fmaxf(mx, fmaxf(fmaxf(v[i].x, v[i].y), fmaxf(v[i].z, v[i].w)));
    mx = blockMax256(mx);

    float s = 0.0f;
    #pragma unroll
    for (int i = 0; i < 4; i++) {
        v[i].x = expf(v[i].x - mx); v[i].y = expf(v[i].y - mx);
        v[i].z = expf(v[i].z - mx); v[i].w = expf(v[i].w - mx);
        s += (v[i].x + v[i].y) + (v[i].z + v[i].w);
    }
    s = blockSum256(s);
    float inv = 1.0f / s;

    float q = 0.0f;
    #pragma unroll
    for (int i = 0; i < 4; i++) {
        float px = v[i].x * inv, py = v[i].y * inv, pz = v[i].z * inv, pw = v[i].w * inv;
        q += px * px + py * py + pz * pz + pw * pw;
        __half2 h0 = __floats2half2_rn(px * SCALE, py * SCALE);
        __half2 h1 = __floats2half2_rn(pz * SCALE, pw * SCALE);
        uint2 o;
        o.x = *(uint32_t*)&h0;
        o.y = *(uint32_t*)&h1;
        wp[threadIdx.x + i * 256] = o;
    }
    q = blockSum256(q);
    if (threadIdx.x == 0) sq[row] = q;
}

// ---------------- 2) fp16 mma.sync GEMM + epilogue C = x2+y2-2G + fused colsum ----------------
// CTA tile 128x128, K-chunk 64, 3-stage cp.async pipeline, 256 threads.
// Warps: 4(M) x 2(N), each warp owns 32x64 (2 m16 x 8 n8 mma tiles).
#define BKC 64
#define KT (NN / BKC)          // 64
#define STAGE_BYTES 32768u     // 16KB A + 16KB B
#define SMEM_TOTAL  (3 * STAGE_BYTES)   // 96KB

__global__ __launch_bounds__(256, 2) void gemm_kernel(float* __restrict__ C) {
    extern __shared__ __align__(128) char dyn[];
    __shared__ float part[8][64];
    uint32_t sbase = smem_u32(dyn);

    int tid = threadIdx.x, warp = tid >> 5, lane = tid & 31;

    // grouped rasterization for L2 reuse
    int bid = blockIdx.x;
    const int TILES = NN / 128;  // 32
    const int GROUP = 8;
    int width = GROUP * TILES;
    int g = bid / width;
    int r = bid % width;
    int bm = g * GROUP + (r % GROUP);
    int bn = r / GROUP;
    int rowBase = bm * 128, colBase = bn * 128;

    int wm = warp >> 1;        // 0..3  (M)
    int wn = warp & 1;         // 0..1  (N)

    float acc[2][8][4];
    #pragma unroll
    for (int mt = 0; mt < 2; mt++)
        #pragma unroll
        for (int nt = 0; nt < 8; nt++)
            #pragma unroll
            for (int e = 0; e < 4; e++) acc[mt][nt][e] = 0.0f;

    auto issue = [&](int s, int kt) {
        uint32_t smA = sbase + (uint32_t)s * STAGE_BYTES;
        uint32_t smB = smA + 16384u;
        int k0 = kt * BKC;
        #pragma unroll
        for (int i = 0; i < 4; i++) {
            int lin = tid + i * 256;
            int row = lin >> 3, ch = lin & 7;
            uint32_t phys = (uint32_t)row * 128u + (uint32_t)((ch ^ (row & 7)) << 4);
            cp_async16(smA + phys, (const char*)(g_xs16 + (size_t)(rowBase + row) * NN + k0) + ch * 16);
            cp_async16(smB + phys, (const char*)(g_ys16 + (size_t)(colBase + row) * NN + k0) + ch * 16);
        }
        CP_COMMIT();
    };

    issue(0, 0);
    issue(1, 1);

    // ldmatrix lane bases
    int aRowSel = (lane & 7) + ((lane >> 3) & 1) * 8;
    int aChSel  = (lane >> 4);
    int bColSel = ((lane >> 4) & 1) * 8 + (lane & 7);
    int bChSel  = (lane >> 3) & 1;

    for (int kt = 0; kt < KT; kt++) {
        // issue ahead FIRST, then wait only for chunk kt
        if (kt + 2 < KT) {
            issue((kt + 2) % 3, kt + 2);
            CP_WAIT2();
        } else if (kt + 1 < KT) {
            CP_WAIT1();
        } else {
            CP_WAIT0();
        }
        __syncthreads();

        uint32_t aBase = sbase + (uint32_t)(kt % 3) * STAGE_BYTES;
        uint32_t bBase = aBase + 16384u;

        #pragma unroll
        for (int kk = 0; kk < 4; kk++) {
            uint32_t a[2][4];
            #pragma unroll
            for (int mt = 0; mt < 2; mt++) {
                int rowL = wm * 32 + mt * 16 + aRowSel;
                int ch = 2 * kk + aChSel;
                uint32_t addr = aBase + (uint32_t)rowL * 128u + (uint32_t)((ch ^ (rowL & 7)) << 4);
                LDSM_X4(a[mt][0], a[mt][1], a[mt][2], a[mt][3], addr);
            }
            uint32_t b[8][2];
            #pragma unroll
            for (int np = 0; np < 4; np++) {
                int colL = wn * 64 + np * 16 + bColSel;
                int ch = 2 * kk + bChSel;
                uint32_t addr = bBase + (uint32_t)colL * 128u + (uint32_t)((ch ^ (colL & 7)) << 4);
                uint32_t r0, r1, r2, r3;
                LDSM_X4(r0, r1, r2, r3, addr);
                b[2 * np][0] = r0; b[2 * np][1] = r1;
                b[2 * np + 1][0] = r2; b[2 * np + 1][1] = r3;
            }
            #pragma unroll
            for (int mt = 0; mt < 2; mt++)
                #pragma unroll
                for (int nt = 0; nt < 8; nt++)
                    MMA16816(acc[mt][nt], a[mt], b[nt]);
        }
        __syncthreads();
    }

    // ---------------- epilogue: C = x2+y2-2G, fused column-sums of exp(-10C) ----------------
    float* stg = (float*)dyn + warp * (32 * 66);
    int rsel = lane >> 2, csel = (lane & 3) * 2;
    #pragma unroll
    for (int mt = 0; mt < 2; mt++) {
        #pragma unroll
        for (int nt = 0; nt < 8; nt++) {
            stg[(mt * 16 + rsel) * 66 + nt * 8 + csel]     = acc[mt][nt][0];
            stg[(mt * 16 + rsel) * 66 + nt * 8 + csel + 1] = acc[mt][nt][1];
            stg[(mt * 16 + rsel + 8) * 66 + nt * 8 + csel]     = acc[mt][nt][2];
            stg[(mt * 16 + rsel + 8) * 66 + nt * 8 + csel + 1] = acc[mt][nt][3];
        }
    }
    __syncwarp();

    int growBase = rowBase + wm * 32;
    int gcol = colBase + wn * 64 + 2 * lane;
    float y0 = g_y2[gcol], y1 = g_y2[gcol + 1];
    float sexp0 = 0.0f, sexp1 = 0.0f;
    #pragma unroll 4
    for (int rr = 0; rr < 32; rr++) {
        int grow = growBase + rr;
        float xv = g_x2[grow];
        float v0 = xv + y0 - 2.0f * INV_S2 * stg[rr * 66 + 2 * lane];
        float v1 = xv + y1 - 2.0f * INV_S2 * stg[rr * 66 + 2 * lane + 1];
        float* cp = C + (size_t)grow * NN + gcol;
        cp[0] = v0;
        cp[1] = v1;
        sexp0 += expf(-10.0f * v0);
        sexp1 += expf(-10.0f * v1);
    }
    part[warp][2 * lane]     = sexp0;
    part[warp][2 * lane + 1] = sexp1;
    __syncthreads();
    if (tid < 128) {
        int wnq = tid >> 6, cl = tid & 63;
        float s = part[wnq][cl] + part[2 + wnq][cl] + part[4 + wnq][cl] + part[6 + wnq][cl];
        g_sum_part[(size_t)bm * NN + colBase + wnq * 64 + cl] = s;
    }
}

// ---------------- 3) combine column sums -> w ----------------
__global__ void combine_sum_kernel() {
    int col = blockIdx.x * 256 + threadIdx.x;
    float S = 0.0f;
    #pragma unroll
    for (int i = 0; i < 32; i++) S += g_sum_part[(size_t)i * NN + col];
    float log_nu = logf(1.0f / 4096.0f + 1e-8f);
    g_w10[col] = log_nu - logf(S);
}

// ---------------- 4) pi = exp(-10*C + w10[j]); cost = sum(pi*C) ----------------
__global__ void pi_cost_kernel(const float* __restrict__ C, float* __restrict__ pi) {
    __shared__ float w[NN];
    int row = blockIdx.x;
    for (int i = threadIdx.x; i < NN; i += 256) w[i] = g_w10[i];
    __syncthreads();

    const float* cr = C + (size_t)row * NN;
    float* pr = pi + (size_t)row * NN;
    float lc = 0.0f;
    #pragma unroll
    for (int i = 0; i < 16; i++) {
        int j = threadIdx.x + i * 256;
        float c = cr[j];
        float p = expf(fmaf(-10.0f, c, w[j]));
        pr[j] = p;
        lc = fmaf(p, c, lc);
    }
    lc = blockSum256(lc);
    if (threadIdx.x == 0) g_cost_part[row] = lc;
}

__global__ void cost_final_kernel(float* __restrict__ out) {
    float s = 0.0f;
    for (int i = threadIdx.x; i < NN; i += 256) s += g_cost_part[i];
    s = blockSum256(s);
    if (threadIdx.x == 0) out[0] = s;
}

// ---------------- launch ----------------
extern "C" void kernel_launch(void* const* d_in, const int* in_sizes, int n_in,
                              void* d_out, int out_size) {
    const float* x = (const float*)d_in[0];
    const float* y = (const float*)d_in[1];
    float* out = (float*)d_out;
    float* pi = out + 1;                        // [N*N]
    float* C  = out + 1 + (size_t)NN * NN;      // [N*N]

    cudaFuncSetAttribute(gemm_kernel, cudaFuncAttributeMaxDynamicSharedMemorySize, SMEM_TOTAL);

    softmax_kernel<<<2 * NN, 256>>>(x, y);

    gemm_kernel<<<(NN / 128) * (NN / 128), 256, SMEM_TOTAL>>>(C);

    combine_sum_kernel<<<NN / 256, 256>>>();

    pi_cost_kernel<<<NN, 256>>>(C, pi);
    cost_final_kernel<<<1, 256>>>(out);
}

// round 7
// speedup vs baseline: 5.1211x; 1.0385x over previous
#include <cuda_runtime.h>
#include <cuda_fp16.h>
#include <cstdint>

#define NN 4096
#define SCALE 1024.0f
#define INV_S2 (1.0f / (1024.0f * 1024.0f))
#define L2E 1.4426950408889634f

// ---------------- scratch (static device globals; no allocation) ----------------
__device__ __half g_xs16[(size_t)NN * NN];   // softmaxed x * SCALE, fp16
__device__ __half g_ys16[(size_t)NN * NN];   // softmaxed y * SCALE, fp16
__device__ float g_x2[NN];
__device__ float g_y2[NN];
__device__ float g_sum_part[32 * NN];
__device__ float g_w10[NN];                  // log_nu - L_j  (== w_j / eps)
__device__ float g_cost_part[1024];

// ---------------- PTX helpers ----------------
__device__ __forceinline__ uint32_t smem_u32(const void* p) {
    uint32_t a;
    asm("{ .reg .u64 t; cvta.to.shared.u64 t, %1; cvt.u32.u64 %0, t; }" : "=r"(a) : "l"(p));
    return a;
}

__device__ __forceinline__ float fast_ex2(float x) {
    float r;
    asm("ex2.approx.ftz.f32 %0, %1;" : "=f"(r) : "f"(x));
    return r;
}

__device__ __forceinline__ void cp_async16(uint32_t smem_dst, const void* gmem_src) {
    asm volatile("cp.async.cg.shared.global [%0], [%1], 16;\n" :: "r"(smem_dst), "l"(gmem_src));
}
#define CP_COMMIT() asm volatile("cp.async.commit_group;\n" ::: "memory")
#define CP_WAIT1()  asm volatile("cp.async.wait_group 1;\n" ::: "memory")
#define CP_WAIT0()  asm volatile("cp.async.wait_group 0;\n" ::: "memory")

#define LDSM_X4(r0, r1, r2, r3, addr) \
    asm volatile("ldmatrix.sync.aligned.m8n8.x4.shared.b16 {%0,%1,%2,%3}, [%4];" \
        : "=r"(r0), "=r"(r1), "=r"(r2), "=r"(r3) : "r"(addr))

#define MMA16816(d, a, b) \
    asm volatile("mma.sync.aligned.m16n8k16.row.col.f32.f16.f16.f32 " \
        "{%0,%1,%2,%3}, {%4,%5,%6,%7}, {%8,%9}, {%0,%1,%2,%3};" \
        : "+f"((d)[0]), "+f"((d)[1]), "+f"((d)[2]), "+f"((d)[3]) \
        : "r"((a)[0]), "r"((a)[1]), "r"((a)[2]), "r"((a)[3]), "r"((b)[0]), "r"((b)[1]))

// ---------------- block reductions ----------------
__device__ __forceinline__ float blockSum256(float v) {
    __shared__ float sm[8];
    int lane = threadIdx.x & 31, w = threadIdx.x >> 5;
    #pragma unroll
    for (int o = 16; o > 0; o >>= 1) v += __shfl_xor_sync(0xffffffffu, v, o);
    if (lane == 0) sm[w] = v;
    __syncthreads();
    if (w == 0) {
        v = (lane < 8) ? sm[lane] : 0.0f;
        #pragma unroll
        for (int o = 4; o > 0; o >>= 1) v += __shfl_xor_sync(0xffffffffu, v, o);
        if (lane == 0) sm[0] = v;
    }
    __syncthreads();
    float r = sm[0];
    __syncthreads();
    return r;
}

__device__ __forceinline__ float blockMax256(float v) {
    __shared__ float sm[8];
    int lane = threadIdx.x & 31, w = threadIdx.x >> 5;
    #pragma unroll
    for (int o = 16; o > 0; o >>= 1) v = fmaxf(v, __shfl_xor_sync(0xffffffffu, v, o));
    if (lane == 0) sm[w] = v;
    __syncthreads();
    if (w == 0) {
        v = (lane < 8) ? sm[lane] : -3.4e38f;
        #pragma unroll
        for (int o = 4; o > 0; o >>= 1) v = fmaxf(v, __shfl_xor_sync(0xffffffffu, v, o));
        if (lane == 0) sm[0] = v;
    }
    __syncthreads();
    float r = sm[0];
    __syncthreads();
    return r;
}

// ---------------- 1) row softmax -> fp16*SCALE + sum of squares (x and y in one grid) ----------------
__global__ void softmax_kernel(const float* __restrict__ xin, const float* __restrict__ yin) {
    int which = (blockIdx.x >= NN);
    int row = blockIdx.x - which * NN;
    const float* in = which ? yin : xin;
    __half* outp = which ? g_ys16 : g_xs16;
    float* sq    = which ? g_y2 : g_x2;
    const float4* rp = (const float4*)(in + (size_t)row * NN);
    uint2* wp = (uint2*)(outp + (size_t)row * NN);

    float4 v[4];
    #pragma unroll
    for (int i = 0; i < 4; i++) v[i] = rp[threadIdx.x + i * 256];

    float mx = -3.4e38f;
    #pragma unroll
    for (int i = 0; i < 4; i++)
        mx = fmaxf(mx, fmaxf(fmaxf(v[i].x, v[i].y), fmaxf(v[i].z, v[i].w)));
    mx = blockMax256(mx);

    float s = 0.0f;
    #pragma unroll
    for (int i = 0; i < 4; i++) {
        v[i].x = fast_ex2((v[i].x - mx) * L2E);
        v[i].y = fast_ex2((v[i].y - mx) * L2E);
        v[i].z = fast_ex2((v[i].z - mx) * L2E);
        v[i].w = fast_ex2((v[i].w - mx) * L2E);
        s += (v[i].x + v[i].y) + (v[i].z + v[i].w);
    }
    s = blockSum256(s);
    float inv = 1.0f / s;

    float q = 0.0f;
    #pragma unroll
    for (int i = 0; i < 4; i++) {
        float px = v[i].x * inv, py = v[i].y * inv, pz = v[i].z * inv, pw = v[i].w * inv;
        q += px * px + py * py + pz * pz + pw * pw;
        __half2 h0 = __floats2half2_rn(px * SCALE, py * SCALE);
        __half2 h1 = __floats2half2_rn(pz * SCALE, pw * SCALE);
        uint2 o;
        o.x = *(uint32_t*)&h0;
        o.y = *(uint32_t*)&h1;
        wp[threadIdx.x + i * 256] = o;
    }
    q = blockSum256(q);
    if (threadIdx.x == 0) sq[row] = q;
}

// ---------------- 2) fp16 mma.sync GEMM + epilogue C = x2+y2-2G + fused colsum ----------------
#define BKC 64
#define KT (NN / BKC)          // 64
#define STAGE_BYTES 32768u     // 16KB A + 16KB B
#define SMEM_TOTAL  (3 * STAGE_BYTES)   // 96KB

__global__ __launch_bounds__(256, 2) void gemm_kernel(float* __restrict__ C) {
    extern __shared__ __align__(128) char dyn[];
    __shared__ float part[8][64];
    uint32_t sbase = smem_u32(dyn);

    int tid = threadIdx.x, warp = tid >> 5, lane = tid & 31;

    int bid = blockIdx.x;
    const int TILES = NN / 128;  // 32
    const int GROUP = 8;
    int width = GROUP * TILES;
    int g = bid / width;
    int r = bid % width;
    int bm = g * GROUP + (r % GROUP);
    int bn = r / GROUP;
    int rowBase = bm * 128, colBase = bn * 128;

    int wm = warp >> 1;
    int wn = warp & 1;

    float acc[2][8][4];
    #pragma unroll
    for (int mt = 0; mt < 2; mt++)
        #pragma unroll
        for (int nt = 0; nt < 8; nt++)
            #pragma unroll
            for (int e = 0; e < 4; e++) acc[mt][nt][e] = 0.0f;

    auto issue = [&](int s, int kt) {
        uint32_t smA = sbase + (uint32_t)s * STAGE_BYTES;
        uint32_t smB = smA + 16384u;
        int k0 = kt * BKC;
        #pragma unroll
        for (int i = 0; i < 4; i++) {
            int lin = tid + i * 256;
            int row = lin >> 3, ch = lin & 7;
            uint32_t phys = (uint32_t)row * 128u + (uint32_t)((ch ^ (row & 7)) << 4);
            cp_async16(smA + phys, (const char*)(g_xs16 + (size_t)(rowBase + row) * NN + k0) + ch * 16);
            cp_async16(smB + phys, (const char*)(g_ys16 + (size_t)(colBase + row) * NN + k0) + ch * 16);
        }
        CP_COMMIT();
    };

    issue(0, 0);
    issue(1, 1);

    int aRowSel = (lane & 7) + ((lane >> 3) & 1) * 8;
    int aChSel  = (lane >> 4);
    int bColSel = ((lane >> 4) & 1) * 8 + (lane & 7);
    int bChSel  = (lane >> 3) & 1;

    for (int kt = 0; kt < KT; kt++) {
        // wait for chunk kt, publish via single barrier, then issue kt+2 (safe: barrier
        // proves all warps finished reading stage (kt+2)%3 == (kt-1)%3 in iter kt-1)
        if (kt == KT - 1) { CP_WAIT0(); } else { CP_WAIT1(); }
        __syncthreads();
        if (kt + 2 < KT) issue((kt + 2) % 3, kt + 2);

        uint32_t aBase = sbase + (uint32_t)(kt % 3) * STAGE_BYTES;
        uint32_t bBase = aBase + 16384u;

        #pragma unroll
        for (int kk = 0; kk < 4; kk++) {
            uint32_t a[2][4];
            #pragma unroll
            for (int mt = 0; mt < 2; mt++) {
                int rowL = wm * 32 + mt * 16 + aRowSel;
                int ch = 2 * kk + aChSel;
                uint32_t addr = aBase + (uint32_t)rowL * 128u + (uint32_t)((ch ^ (rowL & 7)) << 4);
                LDSM_X4(a[mt][0], a[mt][1], a[mt][2], a[mt][3], addr);
            }
            uint32_t b[8][2];
            #pragma unroll
            for (int np = 0; np < 4; np++) {
                int colL = wn * 64 + np * 16 + bColSel;
                int ch = 2 * kk + bChSel;
                uint32_t addr = bBase + (uint32_t)colL * 128u + (uint32_t)((ch ^ (colL & 7)) << 4);
                uint32_t r0, r1, r2, r3;
                LDSM_X4(r0, r1, r2, r3, addr);
                b[2 * np][0] = r0; b[2 * np][1] = r1;
                b[2 * np + 1][0] = r2; b[2 * np + 1][1] = r3;
            }
            #pragma unroll
            for (int mt = 0; mt < 2; mt++)
                #pragma unroll
                for (int nt = 0; nt < 8; nt++)
                    MMA16816(acc[mt][nt], a[mt], b[nt]);
        }
    }
    __syncthreads();   // protect smem reuse by epilogue staging

    // ---------------- epilogue: C = x2+y2-2G, fused column-sums of exp(-10C) ----------------
    float* stg = (float*)dyn + warp * (32 * 66);
    int rsel = lane >> 2, csel = (lane & 3) * 2;
    #pragma unroll
    for (int mt = 0; mt < 2; mt++) {
        #pragma unroll
        for (int nt = 0; nt < 8; nt++) {
            stg[(mt * 16 + rsel) * 66 + nt * 8 + csel]     = acc[mt][nt][0];
            stg[(mt * 16 + rsel) * 66 + nt * 8 + csel + 1] = acc[mt][nt][1];
            stg[(mt * 16 + rsel + 8) * 66 + nt * 8 + csel]     = acc[mt][nt][2];
            stg[(mt * 16 + rsel + 8) * 66 + nt * 8 + csel + 1] = acc[mt][nt][3];
        }
    }
    __syncwarp();

    int growBase = rowBase + wm * 32;
    int gcol = colBase + wn * 64 + 2 * lane;
    float y0 = g_y2[gcol], y1 = g_y2[gcol + 1];
    float sexp0 = 0.0f, sexp1 = 0.0f;
    const float NEG10L2E = -10.0f * L2E;
    #pragma unroll 4
    for (int rr = 0; rr < 32; rr++) {
        int grow = growBase + rr;
        float xv = g_x2[grow];
        float v0 = xv + y0 - 2.0f * INV_S2 * stg[rr * 66 + 2 * lane];
        float v1 = xv + y1 - 2.0f * INV_S2 * stg[rr * 66 + 2 * lane + 1];
        float* cp = C + (size_t)grow * NN + gcol;
        cp[0] = v0;
        cp[1] = v1;
        sexp0 += fast_ex2(NEG10L2E * v0);
        sexp1 += fast_ex2(NEG10L2E * v1);
    }
    part[warp][2 * lane]     = sexp0;
    part[warp][2 * lane + 1] = sexp1;
    __syncthreads();
    if (tid < 128) {
        int wnq = tid >> 6, cl = tid & 63;
        float s = part[wnq][cl] + part[2 + wnq][cl] + part[4 + wnq][cl] + part[6 + wnq][cl];
        g_sum_part[(size_t)bm * NN + colBase + wnq * 64 + cl] = s;
    }
}

// ---------------- 3) combine column sums -> w (pre-scaled by log2 e) ----------------
__global__ void combine_sum_kernel() {
    int col = blockIdx.x * 256 + threadIdx.x;
    float S = 0.0f;
    #pragma unroll
    for (int i = 0; i < 32; i++) S += g_sum_part[(size_t)i * NN + col];
    float log_nu = logf(1.0f / 4096.0f + 1e-8f);
    g_w10[col] = (log_nu - logf(S)) * L2E;   // stored in log2 domain
}

// ---------------- 4) pi = exp2(-10*L2E*C + w2[j]); cost = sum(pi*C); 4 rows/block ----------------
__global__ void pi_cost_kernel(const float* __restrict__ C, float* __restrict__ pi) {
    __shared__ float w[NN];
    int row0 = blockIdx.x * 4;
    for (int i = threadIdx.x; i < NN; i += 256) w[i] = g_w10[i];
    __syncthreads();

    const float NEG10L2E = -10.0f * L2E;
    float lc = 0.0f;
    #pragma unroll
    for (int rr = 0; rr < 4; rr++) {
        const float* cr = C + (size_t)(row0 + rr) * NN;
        float* pr = pi + (size_t)(row0 + rr) * NN;
        #pragma unroll
        for (int i = 0; i < 16; i++) {
            int j = threadIdx.x + i * 256;
            float c = cr[j];
            float p = fast_ex2(fmaf(NEG10L2E, c, w[j]));
            pr[j] = p;
            lc = fmaf(p, c, lc);
        }
    }
    lc = blockSum256(lc);
    if (threadIdx.x == 0) g_cost_part[blockIdx.x] = lc;
}

__global__ void cost_final_kernel(float* __restrict__ out) {
    float s = 0.0f;
    for (int i = threadIdx.x; i < 1024; i += 256) s += g_cost_part[i];
    s = blockSum256(s);
    if (threadIdx.x == 0) out[0] = s;
}

// ---------------- launch ----------------
extern "C" void kernel_launch(void* const* d_in, const int* in_sizes, int n_in,
                              void* d_out, int out_size) {
    const float* x = (const float*)d_in[0];
    const float* y = (const float*)d_in[1];
    float* out = (float*)d_out;
    float* pi = out + 1;                        // [N*N]
    float* C  = out + 1 + (size_t)NN * NN;      // [N*N]

    cudaFuncSetAttribute(gemm_kernel, cudaFuncAttributeMaxDynamicSharedMemorySize, SMEM_TOTAL);

    softmax_kernel<<<2 * NN, 256>>>(x, y);

    gemm_kernel<<<(NN / 128) * (NN / 128), 256, SMEM_TOTAL>>>(C);

    combine_sum_kernel<<<NN / 256, 256>>>();

    pi_cost_kernel<<<1024, 256>>>(C, pi);
    cost_final_kernel<<<1, 256>>>(out);
}